// round 10
// baseline (speedup 1.0000x reference)
#include <cuda_runtime.h>
#include <math.h>

// Problem constants (fixed by the dataset)
#define B_TOK 8192
#define D_DIM 3072
#define N_EXP 8
#define H_DIM 128
#define O_DIM 10

// GEMM tiling
#define BM 128          // tokens per tile
#define BK 16           // K-slab
// BN == H_DIM == 128 (full H covered by one tile)

// ---------------- device scratch (allocation-free rule: __device__ globals) ----
__device__ int   g_counts[N_EXP];
__device__ int   g_tok[N_EXP * B_TOK];     // packed: (token << 1) | slot
__device__ float g_wt [N_EXP * B_TOK];     // gate weight for that (token, slot)
__device__ float g_ypair[B_TOK * 2 * O_DIM];

__device__ __forceinline__ float f4_get(const float4& v, int j) {
    switch (j) { case 0: return v.x; case 1: return v.y; case 2: return v.z; default: return v.w; }
}

// ---------------- kernel 0: zero the dispatch counters ------------------------
__global__ void zero_counts_kernel() {
    if (threadIdx.x < N_EXP) g_counts[threadIdx.x] = 0;
}

// ---------------- kernel 1: gating (fp32, exact routing) ----------------------
// One warp handles 4 tokens (amortizes Wg loads 4x). 8 logits per token via
// lane-strided fp32 dots, warp shfl reduce, then top-2 + softmax + dispatch.
__global__ __launch_bounds__(256) void gate_kernel(
    const float* __restrict__ x,
    const float* __restrict__ Wg,
    const float* __restrict__ bg)
{
    int gw   = (blockIdx.x * blockDim.x + threadIdx.x) >> 5;
    int lane = threadIdx.x & 31;
    int b0   = gw * 4;
    if (b0 >= B_TOK) return;

    float acc[4][8];
    #pragma unroll
    for (int t = 0; t < 4; ++t)
        #pragma unroll
        for (int e = 0; e < 8; ++e) acc[t][e] = 0.f;

    const float4* Wg4 = reinterpret_cast<const float4*>(Wg);

    for (int d4 = lane; d4 < D_DIM / 4; d4 += 32) {
        float4 xv[4];
        #pragma unroll
        for (int t = 0; t < 4; ++t)
            xv[t] = reinterpret_cast<const float4*>(x + (size_t)(b0 + t) * D_DIM)[d4];
        #pragma unroll
        for (int j = 0; j < 4; ++j) {
            float4 wa = Wg4[(size_t)(d4 * 4 + j) * 2 + 0];
            float4 wb = Wg4[(size_t)(d4 * 4 + j) * 2 + 1];
            #pragma unroll
            for (int t = 0; t < 4; ++t) {
                float xs = f4_get(xv[t], j);
                acc[t][0] = fmaf(xs, wa.x, acc[t][0]);
                acc[t][1] = fmaf(xs, wa.y, acc[t][1]);
                acc[t][2] = fmaf(xs, wa.z, acc[t][2]);
                acc[t][3] = fmaf(xs, wa.w, acc[t][3]);
                acc[t][4] = fmaf(xs, wb.x, acc[t][4]);
                acc[t][5] = fmaf(xs, wb.y, acc[t][5]);
                acc[t][6] = fmaf(xs, wb.z, acc[t][6]);
                acc[t][7] = fmaf(xs, wb.w, acc[t][7]);
            }
        }
    }

    // warp reduce all 32 partial sums
    #pragma unroll
    for (int off = 16; off > 0; off >>= 1)
        #pragma unroll
        for (int t = 0; t < 4; ++t)
            #pragma unroll
            for (int e = 0; e < 8; ++e)
                acc[t][e] += __shfl_xor_sync(0xffffffffu, acc[t][e], off);

    if (lane == 0) {
        #pragma unroll
        for (int t = 0; t < 4; ++t) {
            float g[8];
            #pragma unroll
            for (int e = 0; e < 8; ++e) g[e] = acc[t][e] + bg[e];

            // top-2, stable (lowest index wins ties) == jax.lax.top_k semantics
            int i0 = 0;
            #pragma unroll
            for (int e = 1; e < 8; ++e) if (g[e] > g[i0]) i0 = e;
            int i1 = (i0 == 0) ? 1 : 0;
            #pragma unroll
            for (int e = 0; e < 8; ++e) if (e != i0 && g[e] > g[i1]) i1 = e;

            // softmax over the two selected logits (g[i0] >= g[i1])
            float e1 = expf(g[i1] - g[i0]);
            float s  = 1.0f + e1;
            float w0 = 1.0f / s;
            float w1 = e1 / s;

            int tok = b0 + t;
            int p0 = atomicAdd(&g_counts[i0], 1);
            g_tok[i0 * B_TOK + p0] = (tok << 1) | 0;
            g_wt [i0 * B_TOK + p0] = w0;
            int p1 = atomicAdd(&g_counts[i1], 1);
            g_tok[i1 * B_TOK + p1] = (tok << 1) | 1;
            g_wt [i1 * B_TOK + p1] = w1;
        }
    }
}

// ---------------- kernel 2: per-expert gathered GEMM1 + ReLU + GEMM2 ----------
// grid = (ceil(B/BM)=64, N_EXP). Blocks past the expert's token count exit.
// 256 threads, 16x16 layout, 8x8 fp32 microtile, double-buffered smem,
// one __syncthreads per K-slab. Epilogue: ReLU, then H->O dot with shfl-xor
// reduction across the 16 n-threads (deterministic, no atomics on data).
__global__ __launch_bounds__(256) void expert_kernel(
    const float* __restrict__ x,
    const float* __restrict__ W1,
    const float* __restrict__ b1,
    const float* __restrict__ W2,
    const float* __restrict__ b2)
{
    const int e   = blockIdx.y;
    const int cnt = g_counts[e];
    const int m0  = blockIdx.x * BM;
    if (m0 >= cnt) return;

    __shared__ __align__(16) float As[2][BK][BM];       // As[k][m]  (x gathered, transposed)
    __shared__ __align__(16) float Bs[2][BK][H_DIM];    // Bs[k][n]  (W1 slab)

    const int t  = threadIdx.x;
    const int tx = t & 15;          // n-thread
    const int ty = t >> 4;          // m-thread

    // ---- A loader state: this thread always loads row mA, k-groups kgA and kgA+2
    const int mA  = t & 127;
    const int kgA = t >> 7;                       // 0 or 1
    const int gmA = m0 + mA;
    const int tokA = (gmA < cnt) ? (g_tok[e * B_TOK + gmA] >> 1) : 0;
    const float4* xrow = reinterpret_cast<const float4*>(x + (size_t)tokA * D_DIM);

    // ---- B loader state: rows kB and kB+8, float4 column nB
    const int kB = t >> 5;                        // 0..7
    const int nB = (t & 31) * 4;
    const float* W1e = W1 + (size_t)e * D_DIM * H_DIM;

    // prologue: slab 0 -> buffer 0
    {
        float4 a0 = xrow[kgA];
        float4 a1 = xrow[kgA + 2];
        float4 w0 = *reinterpret_cast<const float4*>(W1e + (size_t)kB * H_DIM + nB);
        float4 w1 = *reinterpret_cast<const float4*>(W1e + (size_t)(kB + 8) * H_DIM + nB);
        As[0][kgA * 4 + 0][mA] = a0.x; As[0][kgA * 4 + 1][mA] = a0.y;
        As[0][kgA * 4 + 2][mA] = a0.z; As[0][kgA * 4 + 3][mA] = a0.w;
        As[0][(kgA + 2) * 4 + 0][mA] = a1.x; As[0][(kgA + 2) * 4 + 1][mA] = a1.y;
        As[0][(kgA + 2) * 4 + 2][mA] = a1.z; As[0][(kgA + 2) * 4 + 3][mA] = a1.w;
        *reinterpret_cast<float4*>(&Bs[0][kB][nB])     = w0;
        *reinterpret_cast<float4*>(&Bs[0][kB + 8][nB]) = w1;
    }
    __syncthreads();

    float c[8][8];
    #pragma unroll
    for (int i = 0; i < 8; ++i)
        #pragma unroll
        for (int j = 0; j < 8; ++j) c[i][j] = 0.f;

    const int NK = D_DIM / BK;  // 192
    int cur = 0;

    for (int kt = 1; kt <= NK; ++kt) {
        float4 na0, na1, nw0, nw1;
        if (kt < NK) {
            int k0 = kt * BK;
            na0 = xrow[k0 / 4 + kgA];
            na1 = xrow[k0 / 4 + kgA + 2];
            nw0 = *reinterpret_cast<const float4*>(W1e + (size_t)(k0 + kB) * H_DIM + nB);
            nw1 = *reinterpret_cast<const float4*>(W1e + (size_t)(k0 + kB + 8) * H_DIM + nB);
        }

        #pragma unroll
        for (int k = 0; k < BK; ++k) {
            float4 a0 = *reinterpret_cast<const float4*>(&As[cur][k][ty * 8]);
            float4 a1 = *reinterpret_cast<const float4*>(&As[cur][k][ty * 8 + 4]);
            float4 bb0 = *reinterpret_cast<const float4*>(&Bs[cur][k][tx * 8]);
            float4 bb1 = *reinterpret_cast<const float4*>(&Bs[cur][k][tx * 8 + 4]);
            float av[8] = {a0.x, a0.y, a0.z, a0.w, a1.x, a1.y, a1.z, a1.w};
            float bv[8] = {bb0.x, bb0.y, bb0.z, bb0.w, bb1.x, bb1.y, bb1.z, bb1.w};
            #pragma unroll
            for (int im = 0; im < 8; ++im)
                #pragma unroll
                for (int in = 0; in < 8; ++in)
                    c[im][in] = fmaf(av[im], bv[in], c[im][in]);
        }

        if (kt < NK) {
            int nxt = cur ^ 1;
            As[nxt][kgA * 4 + 0][mA] = na0.x; As[nxt][kgA * 4 + 1][mA] = na0.y;
            As[nxt][kgA * 4 + 2][mA] = na0.z; As[nxt][kgA * 4 + 3][mA] = na0.w;
            As[nxt][(kgA + 2) * 4 + 0][mA] = na1.x; As[nxt][(kgA + 2) * 4 + 1][mA] = na1.y;
            As[nxt][(kgA + 2) * 4 + 2][mA] = na1.z; As[nxt][(kgA + 2) * 4 + 3][mA] = na1.w;
            *reinterpret_cast<float4*>(&Bs[nxt][kB][nB])     = nw0;
            *reinterpret_cast<float4*>(&Bs[nxt][kB + 8][nB]) = nw1;
            __syncthreads();
            cur = nxt;
        }
    }

    // ---- epilogue: bias + ReLU
    {
        float b1v[8];
        #pragma unroll
        for (int in = 0; in < 8; ++in) b1v[in] = b1[e * H_DIM + tx * 8 + in];
        #pragma unroll
        for (int im = 0; im < 8; ++im)
            #pragma unroll
            for (int in = 0; in < 8; ++in)
                c[im][in] = fmaxf(c[im][in] + b1v[in], 0.f);
    }

    // token ids / weights for the rows this (ty) owns — used by writer lanes
    const bool writer = (tx == 0);
    int   tpk[8];
    float wk [8];
    if (writer) {
        #pragma unroll
        for (int im = 0; im < 8; ++im) {
            int gm = m0 + ty * 8 + im;
            if (gm < cnt) {
                tpk[im] = g_tok[e * B_TOK + gm];
                wk [im] = g_wt [e * B_TOK + gm];
            } else { tpk[im] = 0; wk[im] = 0.f; }
        }
    }

    // ---- second GEMM: y[m][o] = sum_h relu_h * W2[e][h][o], reduced via shfl
    const float* W2e = W2 + (size_t)e * H_DIM * O_DIM;
    const float* b2e = b2 + e * O_DIM;

    #pragma unroll 1
    for (int o = 0; o < O_DIM; ++o) {
        float w2v[8];
        #pragma unroll
        for (int in = 0; in < 8; ++in) w2v[in] = W2e[(size_t)(tx * 8 + in) * O_DIM + o];

        float p[8];
        #pragma unroll
        for (int im = 0; im < 8; ++im) {
            float s = 0.f;
            #pragma unroll
            for (int in = 0; in < 8; ++in) s = fmaf(c[im][in], w2v[in], s);
            p[im] = s;
        }
        // reduce across the 16 tx threads (stays within half-warp, deterministic)
        #pragma unroll
        for (int off = 1; off < 16; off <<= 1)
            #pragma unroll
            for (int im = 0; im < 8; ++im)
                p[im] += __shfl_xor_sync(0xffffffffu, p[im], off);

        if (writer) {
            float bb = b2e[o];
            #pragma unroll
            for (int im = 0; im < 8; ++im) {
                int gm = m0 + ty * 8 + im;
                if (gm < cnt)
                    g_ypair[(size_t)tpk[im] * O_DIM + o] = wk[im] * (p[im] + bb);
            }
        }
    }
}

// ---------------- kernel 3: combine the two expert contributions --------------
__global__ void combine_kernel(float* __restrict__ out) {
    int i = blockIdx.x * blockDim.x + threadIdx.x;
    if (i < B_TOK * O_DIM) {
        int b = i / O_DIM, o = i - b * O_DIM;
        out[i] = g_ypair[b * 2 * O_DIM + o] + g_ypair[(b * 2 + 1) * O_DIM + o];
    }
}

// ---------------- launch -------------------------------------------------------
extern "C" void kernel_launch(void* const* d_in, const int* in_sizes, int n_in,
                              void* d_out, int out_size) {
    (void)in_sizes; (void)n_in; (void)out_size;
    const float* x  = (const float*)d_in[0];
    const float* Wg = (const float*)d_in[1];
    const float* bg = (const float*)d_in[2];
    const float* W1 = (const float*)d_in[3];
    const float* b1 = (const float*)d_in[4];
    const float* W2 = (const float*)d_in[5];
    const float* b2 = (const float*)d_in[6];
    float* out = (float*)d_out;

    zero_counts_kernel<<<1, 32>>>();

    // 8192 tokens / 4 per warp / 8 warps per block = 256 blocks
    gate_kernel<<<256, 256>>>(x, Wg, bg);

    dim3 eg(B_TOK / BM, N_EXP);   // (64, 8); blocks past count exit immediately
    expert_kernel<<<eg, 256>>>(x, W1, b1, W2, b2);

    combine_kernel<<<(B_TOK * O_DIM + 255) / 256, 256>>>(out);
}

// round 11
// speedup vs baseline: 1.0035x; 1.0035x over previous
#include <cuda_runtime.h>
#include <math.h>

// Problem constants (fixed by the dataset)
#define B_TOK 8192
#define D_DIM 3072
#define N_EXP 8
#define H_DIM 128
#define O_DIM 10

// GEMM tiling
#define BM 128          // tokens per tile
#define BK 16           // K-slab
// BN == H_DIM == 128 (full H covered by one tile)

// ---------------- device scratch (allocation-free rule: __device__ globals) ----
__device__ int   g_counts[N_EXP];
__device__ int   g_tok[N_EXP * B_TOK];     // packed: (token << 1) | slot
__device__ float g_wt [N_EXP * B_TOK];     // gate weight for that (token, slot)
__device__ float g_ypair[B_TOK * 2 * O_DIM];

__device__ __forceinline__ float f4_get(const float4& v, int j) {
    switch (j) { case 0: return v.x; case 1: return v.y; case 2: return v.z; default: return v.w; }
}

// ---------------- kernel 0: zero the dispatch counters ------------------------
__global__ void zero_counts_kernel() {
    if (threadIdx.x < N_EXP) g_counts[threadIdx.x] = 0;
}

// ---------------- kernel 1: gating (fp32, exact routing) ----------------------
// One warp handles 4 tokens (amortizes Wg loads 4x). 8 logits per token via
// lane-strided fp32 dots, warp shfl reduce, then top-2 + softmax + dispatch.
__global__ __launch_bounds__(256) void gate_kernel(
    const float* __restrict__ x,
    const float* __restrict__ Wg,
    const float* __restrict__ bg)
{
    int gw   = (blockIdx.x * blockDim.x + threadIdx.x) >> 5;
    int lane = threadIdx.x & 31;
    int b0   = gw * 4;
    if (b0 >= B_TOK) return;

    float acc[4][8];
    #pragma unroll
    for (int t = 0; t < 4; ++t)
        #pragma unroll
        for (int e = 0; e < 8; ++e) acc[t][e] = 0.f;

    const float4* Wg4 = reinterpret_cast<const float4*>(Wg);

    for (int d4 = lane; d4 < D_DIM / 4; d4 += 32) {
        float4 xv[4];
        #pragma unroll
        for (int t = 0; t < 4; ++t)
            xv[t] = reinterpret_cast<const float4*>(x + (size_t)(b0 + t) * D_DIM)[d4];
        #pragma unroll
        for (int j = 0; j < 4; ++j) {
            float4 wa = Wg4[(size_t)(d4 * 4 + j) * 2 + 0];
            float4 wb = Wg4[(size_t)(d4 * 4 + j) * 2 + 1];
            #pragma unroll
            for (int t = 0; t < 4; ++t) {
                float xs = f4_get(xv[t], j);
                acc[t][0] = fmaf(xs, wa.x, acc[t][0]);
                acc[t][1] = fmaf(xs, wa.y, acc[t][1]);
                acc[t][2] = fmaf(xs, wa.z, acc[t][2]);
                acc[t][3] = fmaf(xs, wa.w, acc[t][3]);
                acc[t][4] = fmaf(xs, wb.x, acc[t][4]);
                acc[t][5] = fmaf(xs, wb.y, acc[t][5]);
                acc[t][6] = fmaf(xs, wb.z, acc[t][6]);
                acc[t][7] = fmaf(xs, wb.w, acc[t][7]);
            }
        }
    }

    // warp reduce all 32 partial sums
    #pragma unroll
    for (int off = 16; off > 0; off >>= 1)
        #pragma unroll
        for (int t = 0; t < 4; ++t)
            #pragma unroll
            for (int e = 0; e < 8; ++e)
                acc[t][e] += __shfl_xor_sync(0xffffffffu, acc[t][e], off);

    if (lane == 0) {
        #pragma unroll
        for (int t = 0; t < 4; ++t) {
            float g[8];
            #pragma unroll
            for (int e = 0; e < 8; ++e) g[e] = acc[t][e] + bg[e];

            // top-2, stable (lowest index wins ties) == jax.lax.top_k semantics
            int i0 = 0;
            #pragma unroll
            for (int e = 1; e < 8; ++e) if (g[e] > g[i0]) i0 = e;
            int i1 = (i0 == 0) ? 1 : 0;
            #pragma unroll
            for (int e = 0; e < 8; ++e) if (e != i0 && g[e] > g[i1]) i1 = e;

            // softmax over the two selected logits (g[i0] >= g[i1])
            float e1 = expf(g[i1] - g[i0]);
            float s  = 1.0f + e1;
            float w0 = 1.0f / s;
            float w1 = e1 / s;

            int tok = b0 + t;
            int p0 = atomicAdd(&g_counts[i0], 1);
            g_tok[i0 * B_TOK + p0] = (tok << 1) | 0;
            g_wt [i0 * B_TOK + p0] = w0;
            int p1 = atomicAdd(&g_counts[i1], 1);
            g_tok[i1 * B_TOK + p1] = (tok << 1) | 1;
            g_wt [i1 * B_TOK + p1] = w1;
        }
    }
}

// ---------------- kernel 2: per-expert gathered GEMM1 + ReLU + GEMM2 ----------
// grid = (ceil(B/BM)=64, N_EXP). Blocks past the expert's token count exit.
// 256 threads, 16x16 layout, 8x8 fp32 microtile, double-buffered smem,
// one __syncthreads per K-slab. Epilogue: ReLU, then H->O dot with shfl-xor
// reduction across the 16 n-threads (deterministic, no atomics on data).
__global__ __launch_bounds__(256) void expert_kernel(
    const float* __restrict__ x,
    const float* __restrict__ W1,
    const float* __restrict__ b1,
    const float* __restrict__ W2,
    const float* __restrict__ b2)
{
    const int e   = blockIdx.y;
    const int cnt = g_counts[e];
    const int m0  = blockIdx.x * BM;
    if (m0 >= cnt) return;

    __shared__ __align__(16) float As[2][BK][BM];       // As[k][m]  (x gathered, transposed)
    __shared__ __align__(16) float Bs[2][BK][H_DIM];    // Bs[k][n]  (W1 slab)

    const int t  = threadIdx.x;
    const int tx = t & 15;          // n-thread
    const int ty = t >> 4;          // m-thread

    // ---- A loader state: this thread always loads row mA, k-groups kgA and kgA+2
    const int mA  = t & 127;
    const int kgA = t >> 7;                       // 0 or 1
    const int gmA = m0 + mA;
    const int tokA = (gmA < cnt) ? (g_tok[e * B_TOK + gmA] >> 1) : 0;
    const float4* xrow = reinterpret_cast<const float4*>(x + (size_t)tokA * D_DIM);

    // ---- B loader state: rows kB and kB+8, float4 column nB
    const int kB = t >> 5;                        // 0..7
    const int nB = (t & 31) * 4;
    const float* W1e = W1 + (size_t)e * D_DIM * H_DIM;

    // prologue: slab 0 -> buffer 0
    {
        float4 a0 = xrow[kgA];
        float4 a1 = xrow[kgA + 2];
        float4 w0 = *reinterpret_cast<const float4*>(W1e + (size_t)kB * H_DIM + nB);
        float4 w1 = *reinterpret_cast<const float4*>(W1e + (size_t)(kB + 8) * H_DIM + nB);
        As[0][kgA * 4 + 0][mA] = a0.x; As[0][kgA * 4 + 1][mA] = a0.y;
        As[0][kgA * 4 + 2][mA] = a0.z; As[0][kgA * 4 + 3][mA] = a0.w;
        As[0][(kgA + 2) * 4 + 0][mA] = a1.x; As[0][(kgA + 2) * 4 + 1][mA] = a1.y;
        As[0][(kgA + 2) * 4 + 2][mA] = a1.z; As[0][(kgA + 2) * 4 + 3][mA] = a1.w;
        *reinterpret_cast<float4*>(&Bs[0][kB][nB])     = w0;
        *reinterpret_cast<float4*>(&Bs[0][kB + 8][nB]) = w1;
    }
    __syncthreads();

    float c[8][8];
    #pragma unroll
    for (int i = 0; i < 8; ++i)
        #pragma unroll
        for (int j = 0; j < 8; ++j) c[i][j] = 0.f;

    const int NK = D_DIM / BK;  // 192
    int cur = 0;

    for (int kt = 1; kt <= NK; ++kt) {
        float4 na0, na1, nw0, nw1;
        if (kt < NK) {
            int k0 = kt * BK;
            na0 = xrow[k0 / 4 + kgA];
            na1 = xrow[k0 / 4 + kgA + 2];
            nw0 = *reinterpret_cast<const float4*>(W1e + (size_t)(k0 + kB) * H_DIM + nB);
            nw1 = *reinterpret_cast<const float4*>(W1e + (size_t)(k0 + kB + 8) * H_DIM + nB);
        }

        #pragma unroll
        for (int k = 0; k < BK; ++k) {
            float4 a0 = *reinterpret_cast<const float4*>(&As[cur][k][ty * 8]);
            float4 a1 = *reinterpret_cast<const float4*>(&As[cur][k][ty * 8 + 4]);
            float4 bb0 = *reinterpret_cast<const float4*>(&Bs[cur][k][tx * 8]);
            float4 bb1 = *reinterpret_cast<const float4*>(&Bs[cur][k][tx * 8 + 4]);
            float av[8] = {a0.x, a0.y, a0.z, a0.w, a1.x, a1.y, a1.z, a1.w};
            float bv[8] = {bb0.x, bb0.y, bb0.z, bb0.w, bb1.x, bb1.y, bb1.z, bb1.w};
            #pragma unroll
            for (int im = 0; im < 8; ++im)
                #pragma unroll
                for (int in = 0; in < 8; ++in)
                    c[im][in] = fmaf(av[im], bv[in], c[im][in]);
        }

        if (kt < NK) {
            int nxt = cur ^ 1;
            As[nxt][kgA * 4 + 0][mA] = na0.x; As[nxt][kgA * 4 + 1][mA] = na0.y;
            As[nxt][kgA * 4 + 2][mA] = na0.z; As[nxt][kgA * 4 + 3][mA] = na0.w;
            As[nxt][(kgA + 2) * 4 + 0][mA] = na1.x; As[nxt][(kgA + 2) * 4 + 1][mA] = na1.y;
            As[nxt][(kgA + 2) * 4 + 2][mA] = na1.z; As[nxt][(kgA + 2) * 4 + 3][mA] = na1.w;
            *reinterpret_cast<float4*>(&Bs[nxt][kB][nB])     = nw0;
            *reinterpret_cast<float4*>(&Bs[nxt][kB + 8][nB]) = nw1;
            __syncthreads();
            cur = nxt;
        }
    }

    // ---- epilogue: bias + ReLU
    {
        float b1v[8];
        #pragma unroll
        for (int in = 0; in < 8; ++in) b1v[in] = b1[e * H_DIM + tx * 8 + in];
        #pragma unroll
        for (int im = 0; im < 8; ++im)
            #pragma unroll
            for (int in = 0; in < 8; ++in)
                c[im][in] = fmaxf(c[im][in] + b1v[in], 0.f);
    }

    // token ids / weights for the rows this (ty) owns — used by writer lanes
    const bool writer = (tx == 0);
    int   tpk[8];
    float wk [8];
    if (writer) {
        #pragma unroll
        for (int im = 0; im < 8; ++im) {
            int gm = m0 + ty * 8 + im;
            if (gm < cnt) {
                tpk[im] = g_tok[e * B_TOK + gm];
                wk [im] = g_wt [e * B_TOK + gm];
            } else { tpk[im] = 0; wk[im] = 0.f; }
        }
    }

    // ---- second GEMM: y[m][o] = sum_h relu_h * W2[e][h][o], reduced via shfl
    const float* W2e = W2 + (size_t)e * H_DIM * O_DIM;
    const float* b2e = b2 + e * O_DIM;

    #pragma unroll 1
    for (int o = 0; o < O_DIM; ++o) {
        float w2v[8];
        #pragma unroll
        for (int in = 0; in < 8; ++in) w2v[in] = W2e[(size_t)(tx * 8 + in) * O_DIM + o];

        float p[8];
        #pragma unroll
        for (int im = 0; im < 8; ++im) {
            float s = 0.f;
            #pragma unroll
            for (int in = 0; in < 8; ++in) s = fmaf(c[im][in], w2v[in], s);
            p[im] = s;
        }
        // reduce across the 16 tx threads (stays within half-warp, deterministic)
        #pragma unroll
        for (int off = 1; off < 16; off <<= 1)
            #pragma unroll
            for (int im = 0; im < 8; ++im)
                p[im] += __shfl_xor_sync(0xffffffffu, p[im], off);

        if (writer) {
            float bb = b2e[o];
            #pragma unroll
            for (int im = 0; im < 8; ++im) {
                int gm = m0 + ty * 8 + im;
                if (gm < cnt)
                    g_ypair[(size_t)tpk[im] * O_DIM + o] = wk[im] * (p[im] + bb);
            }
        }
    }
}

// ---------------- kernel 3: combine the two expert contributions --------------
__global__ void combine_kernel(float* __restrict__ out) {
    int i = blockIdx.x * blockDim.x + threadIdx.x;
    if (i < B_TOK * O_DIM) {
        int b = i / O_DIM, o = i - b * O_DIM;
        out[i] = g_ypair[b * 2 * O_DIM + o] + g_ypair[(b * 2 + 1) * O_DIM + o];
    }
}

// ---------------- launch -------------------------------------------------------
extern "C" void kernel_launch(void* const* d_in, const int* in_sizes, int n_in,
                              void* d_out, int out_size) {
    (void)in_sizes; (void)n_in; (void)out_size;
    const float* x  = (const float*)d_in[0];
    const float* Wg = (const float*)d_in[1];
    const float* bg = (const float*)d_in[2];
    const float* W1 = (const float*)d_in[3];
    const float* b1 = (const float*)d_in[4];
    const float* W2 = (const float*)d_in[5];
    const float* b2 = (const float*)d_in[6];
    float* out = (float*)d_out;

    zero_counts_kernel<<<1, 32>>>();

    // 8192 tokens / 4 per warp / 8 warps per block = 256 blocks
    gate_kernel<<<256, 256>>>(x, Wg, bg);

    dim3 eg(B_TOK / BM, N_EXP);   // (64, 8); blocks past count exit immediately
    expert_kernel<<<eg, 256>>>(x, W1, b1, W2, b2);

    combine_kernel<<<(B_TOK * O_DIM + 255) / 256, 256>>>(out);
}